// round 7
// baseline (speedup 1.0000x reference)
#include <cuda_runtime.h>
#include <cuda_bf16.h>
#include <cuda_fp16.h>
#include <math.h>

// Rigid-warp + trilinear resample of a 256^3 fp32 volume.
// Pass 1 builds a y/z-duplicated fp16 "quad" volume:
//   g_quad[x][y][z] = ( v[x][y][z],  v[x][y][z+1],
//                       v[x][y+1][z], v[x][y+1][z+1] )   (clamped at edges)
// packed as uint2 (2x half2, 8 bytes). Pass 2 then needs only TWO aligned
// LDG.64 per output (x0-plane and x1-plane) to fetch all 8 taps.
// The voxel->voxel transform is computed per-block (thread 0 -> smem), so
// there is no serial setup kernel. Arithmetic is fp32; tap storage fp16.

#define DIMD 256
#define DIMH 256
#define DIMW 256
#define NVOX (DIMD * DIMH * DIMW)

__device__ uint2 g_quad[NVOX];   // 128 MB static scratch

static __device__ __forceinline__ unsigned int h2_to_u32(__half2 h) {
    return *reinterpret_cast<unsigned int*>(&h);
}
static __device__ __forceinline__ __half2 u32_to_h2(unsigned int u) {
    return *reinterpret_cast<__half2*>(&u);
}

__device__ __forceinline__ void matmul3(const float a[9], const float b[9], float c[9]) {
    #pragma unroll
    for (int i = 0; i < 3; i++)
        #pragma unroll
        for (int j = 0; j < 3; j++)
            c[i * 3 + j] = a[i * 3 + 0] * b[0 * 3 + j]
                         + a[i * 3 + 1] * b[1 * 3 + j]
                         + a[i * 3 + 2] * b[2 * 3 + j];
}

__device__ __forceinline__ void matmul4(const float a[16], const float b[16], float c[16]) {
    #pragma unroll
    for (int i = 0; i < 4; i++)
        #pragma unroll
        for (int j = 0; j < 4; j++)
            c[i * 4 + j] = a[i * 4 + 0] * b[0 * 4 + j]
                         + a[i * 4 + 1] * b[1 * 4 + j]
                         + a[i * 4 + 2] * b[2 * 4 + j]
                         + a[i * 4 + 3] * b[3 * 4 + j];
}

__device__ void inv4(const float m[16], float invOut[16]) {
    float inv[16];
    inv[0]  =  m[5]*m[10]*m[15] - m[5]*m[11]*m[14] - m[9]*m[6]*m[15] +
               m[9]*m[7]*m[14]  + m[13]*m[6]*m[11] - m[13]*m[7]*m[10];
    inv[4]  = -m[4]*m[10]*m[15] + m[4]*m[11]*m[14] + m[8]*m[6]*m[15] -
               m[8]*m[7]*m[14]  - m[12]*m[6]*m[11] + m[12]*m[7]*m[10];
    inv[8]  =  m[4]*m[9]*m[15]  - m[4]*m[11]*m[13] - m[8]*m[5]*m[15] +
               m[8]*m[7]*m[13]  + m[12]*m[5]*m[11] - m[12]*m[7]*m[9];
    inv[12] = -m[4]*m[9]*m[14]  + m[4]*m[10]*m[13] + m[8]*m[5]*m[14] -
               m[8]*m[6]*m[13]  - m[12]*m[5]*m[10] + m[12]*m[6]*m[9];
    inv[1]  = -m[1]*m[10]*m[15] + m[1]*m[11]*m[14] + m[9]*m[2]*m[15] -
               m[9]*m[3]*m[14]  - m[13]*m[2]*m[11] + m[13]*m[3]*m[10];
    inv[5]  =  m[0]*m[10]*m[15] - m[0]*m[11]*m[14] - m[8]*m[2]*m[15] +
               m[8]*m[3]*m[14]  + m[12]*m[2]*m[11] - m[12]*m[3]*m[10];
    inv[9]  = -m[0]*m[9]*m[15]  + m[0]*m[11]*m[13] + m[8]*m[1]*m[15] -
               m[8]*m[3]*m[13]  - m[12]*m[1]*m[11] + m[12]*m[3]*m[9];
    inv[13] =  m[0]*m[9]*m[14]  - m[0]*m[10]*m[13] - m[8]*m[1]*m[14] +
               m[8]*m[2]*m[13]  + m[12]*m[1]*m[10] - m[12]*m[2]*m[9];
    inv[2]  =  m[1]*m[6]*m[15]  - m[1]*m[7]*m[14]  - m[5]*m[2]*m[15] +
               m[5]*m[3]*m[14]  + m[13]*m[2]*m[7]  - m[13]*m[3]*m[6];
    inv[6]  = -m[0]*m[6]*m[15]  + m[0]*m[7]*m[14]  + m[4]*m[2]*m[15] -
               m[4]*m[3]*m[14]  - m[12]*m[2]*m[7]  + m[12]*m[3]*m[6];
    inv[10] =  m[0]*m[5]*m[15]  - m[0]*m[7]*m[13]  - m[4]*m[1]*m[15] +
               m[4]*m[3]*m[13]  + m[12]*m[1]*m[7]  - m[12]*m[3]*m[5];
    inv[14] = -m[0]*m[5]*m[14]  + m[0]*m[6]*m[13]  + m[4]*m[1]*m[14] -
               m[4]*m[2]*m[13]  - m[12]*m[1]*m[6]  + m[12]*m[2]*m[5];
    inv[3]  = -m[1]*m[6]*m[11]  + m[1]*m[7]*m[10]  + m[5]*m[2]*m[11] -
               m[5]*m[3]*m[10]  - m[9]*m[2]*m[7]   + m[9]*m[3]*m[6];
    inv[7]  =  m[0]*m[6]*m[11]  - m[0]*m[7]*m[10]  - m[4]*m[2]*m[11] +
               m[4]*m[3]*m[10]  + m[8]*m[2]*m[7]   - m[8]*m[3]*m[6];
    inv[11] = -m[0]*m[5]*m[11]  + m[0]*m[7]*m[9]   + m[4]*m[1]*m[11] -
               m[4]*m[3]*m[9]   - m[8]*m[1]*m[7]   + m[8]*m[3]*m[5];
    inv[15] =  m[0]*m[5]*m[10]  - m[0]*m[6]*m[9]   - m[4]*m[1]*m[10] +
               m[4]*m[2]*m[9]   + m[8]*m[1]*m[6]   - m[8]*m[2]*m[5];

    float det = m[0]*inv[0] + m[1]*inv[4] + m[2]*inv[8] + m[3]*inv[12];
    det = 1.0f / det;
    #pragma unroll
    for (int i = 0; i < 16; i++) invOut[i] = inv[i] * det;
}

// Compute first 3 rows of inv(flo_v2r) @ T_rig @ ref_v2r into dst[12].
__device__ void compute_T(const float* __restrict__ rot,
                          const float* __restrict__ tra,
                          const float* __restrict__ ref_v2r,
                          const float* __restrict__ flo_v2r,
                          float* dst) {
    float cx = cosf(rot[0]), cy = cosf(rot[1]), cz = cosf(rot[2]);
    float sx = sinf(rot[0]), sy = sinf(rot[1]), sz = sinf(rot[2]);

    float Rx[9] = {1, 0, 0,  0, cx, -sx,  0, sx, cx};
    float Ry[9] = {cy, 0, sy,  0, 1, 0,  -sy, 0, cy};
    float Rz[9] = {cz, -sz, 0,  sz, cz, 0,  0, 0, 1};
    float RxRy[9], R[9];
    matmul3(Rx, Ry, RxRy);
    matmul3(RxRy, Rz, R);

    float Trig[16] = {
        R[0], R[1], R[2], tra[0],
        R[3], R[4], R[5], tra[1],
        R[6], R[7], R[8], tra[2],
        0.f,  0.f,  0.f,  1.f
    };

    float ref[16], flo[16];
    #pragma unroll
    for (int i = 0; i < 16; i++) { ref[i] = ref_v2r[i]; flo[i] = flo_v2r[i]; }

    float flo_inv[16], A[16], T[16];
    inv4(flo, flo_inv);
    matmul4(Trig, ref, A);
    matmul4(flo_inv, A, T);

    #pragma unroll
    for (int i = 0; i < 12; i++) dst[i] = T[i];
}

// Pass 1: build the quad volume. One thread = 4 consecutive z of row (x,y):
// two float4 loads (rows y, y+1) + two clamped scalars, two uint4 stores.
__global__ void __launch_bounds__(256)
build_quads_kernel(const float* __restrict__ X) {
    const int t = blockIdx.x * 256 + threadIdx.x;     // 4-voxel group id
    const int base = t << 2;
    const int z = base & 255;                         // 0..252 step 4
    const int y = (base >> 8) & 255;

    const float4 a = __ldg((const float4*)(X + base));
    const int baseB = (y < 255) ? base + 256 : base;  // row y+1 (clamped)
    const float4 b = __ldg((const float4*)(X + baseB));

    const bool zin = (z < 252);
    const float na = zin ? __ldg(X + base + 4)  : a.w;
    const float nb = zin ? __ldg(X + baseB + 4) : b.w;

    uint4 o0, o1;
    o0.x = h2_to_u32(__floats2half2_rn(a.x, a.y));   // quad z+0: row y pair
    o0.y = h2_to_u32(__floats2half2_rn(b.x, b.y));   //          row y+1 pair
    o0.z = h2_to_u32(__floats2half2_rn(a.y, a.z));   // quad z+1
    o0.w = h2_to_u32(__floats2half2_rn(b.y, b.z));
    o1.x = h2_to_u32(__floats2half2_rn(a.z, a.w));   // quad z+2
    o1.y = h2_to_u32(__floats2half2_rn(b.z, b.w));
    o1.z = h2_to_u32(__floats2half2_rn(a.w, na));    // quad z+3
    o1.w = h2_to_u32(__floats2half2_rn(b.w, nb));

    uint4* dst = (uint4*)(g_quad + base);            // 32B-aligned
    dst[0] = o0;
    dst[1] = o1;
}

// Pass 2: warp + trilinear; 2 aligned LDG.64 per output fetch all 8 taps.
__global__ void __launch_bounds__(256)
warp_trilinear_quad_kernel(float* __restrict__ out,
                           const float* __restrict__ rot,
                           const float* __restrict__ tra,
                           const float* __restrict__ ref_v2r,
                           const float* __restrict__ flo_v2r) {
    __shared__ float sT[12];
    if (threadIdx.x == 0) compute_T(rot, tra, ref_v2r, flo_v2r, sT);
    __syncthreads();

    const int k = threadIdx.x;            // W (stride-1)
    const int j = blockIdx.x & (DIMH - 1);
    const int i = blockIdx.x >> 8;        // D

    const float T00 = sT[0], T01 = sT[1], T02 = sT[2],  T03 = sT[3];
    const float T10 = sT[4], T11 = sT[5], T12 = sT[6],  T13 = sT[7];
    const float T20 = sT[8], T21 = sT[9], T22 = sT[10], T23 = sT[11];

    const float fi = (float)i, fj = (float)j, fk = (float)k;
    const float di = fmaf(T00, fi, fmaf(T01, fj, fmaf(T02, fk, T03)));
    const float dj = fmaf(T10, fi, fmaf(T11, fj, fmaf(T12, fk, T13)));
    const float dk = fmaf(T20, fi, fmaf(T21, fj, fmaf(T22, fk, T23)));

    const int idx = (i << 16) | (j << 8) | k;
    const float MX = 255.f;

    // strictly-interior mask (matches reference: >0 and <= dim-1)
    const bool ok = (di > 0.f) & (dj > 0.f) & (dk > 0.f) &
                    (di <= MX) & (dj <= MX) & (dk <= MX);
    if (!ok) { out[idx] = 0.f; return; }

    const float fx = floorf(di), fy = floorf(dj), fz = floorf(dk);
    const float wcx = di - fx, wcy = dj - fy, wcz = dk - fz;
    const float wfx = 1.f - wcx, wfy = 1.f - wcy, wfz = 1.f - wcz;

    // ok => coords in (0,255], so floor in [0,255]
    const int x0 = (int)fx, y0 = (int)fy, z0 = (int)fz;
    const int x1 = min(x0 + 1, DIMD - 1);

    const int q0 = (x0 << 16) | (y0 << 8) | z0;
    const int q1 = (x1 << 16) | (y0 << 8) | z0;

    // each load: (y0,z0),(y0,z1),(y1,z0),(y1,z1) taps for one x-plane
    const uint2 u0 = __ldg(g_quad + q0);
    const uint2 u1 = __ldg(g_quad + q1);

    const float2 p00 = __half22float2(u32_to_h2(u0.x));  // x0, row y0: (z0,z1)
    const float2 p01 = __half22float2(u32_to_h2(u0.y));  // x0, row y1: (z0,z1)
    const float2 p10 = __half22float2(u32_to_h2(u1.x));  // x1, row y0
    const float2 p11 = __half22float2(u32_to_h2(u1.y));  // x1, row y1

    const float c00 = fmaf(p00.x, wfz, p00.y * wcz);
    const float c01 = fmaf(p01.x, wfz, p01.y * wcz);
    const float c10 = fmaf(p10.x, wfz, p10.y * wcz);
    const float c11 = fmaf(p11.x, wfz, p11.y * wcz);

    const float c0 = fmaf(c00, wfy, c01 * wcy);
    const float c1 = fmaf(c10, wfy, c11 * wcy);

    out[idx] = fmaf(c0, wfx, c1 * wcx);
}

extern "C" void kernel_launch(void* const* d_in, const int* in_sizes, int n_in,
                              void* d_out, int out_size) {
    const float* image = (const float*)d_in[0];
    const float* rot   = (const float*)d_in[1];
    const float* tra   = (const float*)d_in[2];
    const float* refm  = (const float*)d_in[3];
    const float* flom  = (const float*)d_in[4];
    float* out = (float*)d_out;

    build_quads_kernel<<<NVOX / 4 / 256, 256>>>(image);
    warp_trilinear_quad_kernel<<<DIMD * DIMH, DIMW>>>(out, rot, tra, refm, flom);
}

// round 8
// speedup vs baseline: 2.5185x; 2.5185x over previous
#include <cuda_runtime.h>
#include <cuda_bf16.h>
#include <cuda_fp16.h>
#include <math.h>

// Rigid-warp + trilinear resample of a 256^3 fp32 volume.
// Pass 1 (build): z-pair fp16 volume g_pairs[x][y][z] = half2(v[z], v[z+1])
//   + computes the voxel->voxel transform T in block 0 (hidden behind streaming).
// Pass 2 (main): 2 outputs along j per thread; B's y0-rows reuse A's y1-row
//   loads when the packed base indices match (prob ~0.98 for near-identity T).
// Arithmetic fp32; tap storage fp16 (rel_err ~2e-4, threshold 1e-3).

#define DIMD 256
#define DIMH 256
#define DIMW 256
#define NVOX (DIMD * DIMH * DIMW)

__device__ float g_T[12];
__device__ unsigned int g_pairs[NVOX];   // 64 MB static scratch (half2 per voxel)

static __device__ __forceinline__ unsigned int h2_to_u32(__half2 h) {
    return *reinterpret_cast<unsigned int*>(&h);
}
static __device__ __forceinline__ __half2 u32_to_h2(unsigned int u) {
    return *reinterpret_cast<__half2*>(&u);
}

__device__ __forceinline__ void matmul3(const float a[9], const float b[9], float c[9]) {
    #pragma unroll
    for (int i = 0; i < 3; i++)
        #pragma unroll
        for (int j = 0; j < 3; j++)
            c[i * 3 + j] = a[i * 3 + 0] * b[0 * 3 + j]
                         + a[i * 3 + 1] * b[1 * 3 + j]
                         + a[i * 3 + 2] * b[2 * 3 + j];
}

__device__ __forceinline__ void matmul4(const float a[16], const float b[16], float c[16]) {
    #pragma unroll
    for (int i = 0; i < 4; i++)
        #pragma unroll
        for (int j = 0; j < 4; j++)
            c[i * 4 + j] = a[i * 4 + 0] * b[0 * 4 + j]
                         + a[i * 4 + 1] * b[1 * 4 + j]
                         + a[i * 4 + 2] * b[2 * 4 + j]
                         + a[i * 4 + 3] * b[3 * 4 + j];
}

__device__ void inv4(const float m[16], float invOut[16]) {
    float inv[16];
    inv[0]  =  m[5]*m[10]*m[15] - m[5]*m[11]*m[14] - m[9]*m[6]*m[15] +
               m[9]*m[7]*m[14]  + m[13]*m[6]*m[11] - m[13]*m[7]*m[10];
    inv[4]  = -m[4]*m[10]*m[15] + m[4]*m[11]*m[14] + m[8]*m[6]*m[15] -
               m[8]*m[7]*m[14]  - m[12]*m[6]*m[11] + m[12]*m[7]*m[10];
    inv[8]  =  m[4]*m[9]*m[15]  - m[4]*m[11]*m[13] - m[8]*m[5]*m[15] +
               m[8]*m[7]*m[13]  + m[12]*m[5]*m[11] - m[12]*m[7]*m[9];
    inv[12] = -m[4]*m[9]*m[14]  + m[4]*m[10]*m[13] + m[8]*m[5]*m[14] -
               m[8]*m[6]*m[13]  - m[12]*m[5]*m[10] + m[12]*m[6]*m[9];
    inv[1]  = -m[1]*m[10]*m[15] + m[1]*m[11]*m[14] + m[9]*m[2]*m[15] -
               m[9]*m[3]*m[14]  - m[13]*m[2]*m[11] + m[13]*m[3]*m[10];
    inv[5]  =  m[0]*m[10]*m[15] - m[0]*m[11]*m[14] - m[8]*m[2]*m[15] +
               m[8]*m[3]*m[14]  + m[12]*m[2]*m[11] - m[12]*m[3]*m[10];
    inv[9]  = -m[0]*m[9]*m[15]  + m[0]*m[11]*m[13] + m[8]*m[1]*m[15] -
               m[8]*m[3]*m[13]  - m[12]*m[1]*m[11] + m[12]*m[3]*m[9];
    inv[13] =  m[0]*m[9]*m[14]  - m[0]*m[10]*m[13] - m[8]*m[1]*m[14] +
               m[8]*m[2]*m[13]  + m[12]*m[1]*m[10] - m[12]*m[2]*m[9];
    inv[2]  =  m[1]*m[6]*m[15]  - m[1]*m[7]*m[14]  - m[5]*m[2]*m[15] +
               m[5]*m[3]*m[14]  + m[13]*m[2]*m[7]  - m[13]*m[3]*m[6];
    inv[6]  = -m[0]*m[6]*m[15]  + m[0]*m[7]*m[14]  + m[4]*m[2]*m[15] -
               m[4]*m[3]*m[14]  - m[12]*m[2]*m[7]  + m[12]*m[3]*m[6];
    inv[10] =  m[0]*m[5]*m[15]  - m[0]*m[7]*m[13]  - m[4]*m[1]*m[15] +
               m[4]*m[3]*m[13]  + m[12]*m[1]*m[7]  - m[12]*m[3]*m[5];
    inv[14] = -m[0]*m[5]*m[14]  + m[0]*m[6]*m[13]  + m[4]*m[1]*m[14] -
               m[4]*m[2]*m[13]  - m[12]*m[1]*m[6]  + m[12]*m[2]*m[5];
    inv[3]  = -m[1]*m[6]*m[11]  + m[1]*m[7]*m[10]  + m[5]*m[2]*m[11] -
               m[5]*m[3]*m[10]  - m[9]*m[2]*m[7]   + m[9]*m[3]*m[6];
    inv[7]  =  m[0]*m[6]*m[11]  - m[0]*m[7]*m[10]  - m[4]*m[2]*m[11] +
               m[4]*m[3]*m[10]  + m[8]*m[2]*m[7]   - m[8]*m[3]*m[6];
    inv[11] = -m[0]*m[5]*m[11]  + m[0]*m[7]*m[9]   + m[4]*m[1]*m[11] -
               m[4]*m[3]*m[9]   - m[8]*m[1]*m[7]   + m[8]*m[3]*m[5];
    inv[15] =  m[0]*m[5]*m[10]  - m[0]*m[6]*m[9]   - m[4]*m[1]*m[10] +
               m[4]*m[2]*m[9]   + m[8]*m[1]*m[6]   - m[8]*m[2]*m[5];

    float det = m[0]*inv[0] + m[1]*inv[4] + m[2]*inv[8] + m[3]*inv[12];
    det = 1.0f / det;
    #pragma unroll
    for (int i = 0; i < 16; i++) invOut[i] = inv[i] * det;
}

__device__ void compute_T(const float* __restrict__ rot,
                          const float* __restrict__ tra,
                          const float* __restrict__ ref_v2r,
                          const float* __restrict__ flo_v2r) {
    float cx = cosf(rot[0]), cy = cosf(rot[1]), cz = cosf(rot[2]);
    float sx = sinf(rot[0]), sy = sinf(rot[1]), sz = sinf(rot[2]);

    float Rx[9] = {1, 0, 0,  0, cx, -sx,  0, sx, cx};
    float Ry[9] = {cy, 0, sy,  0, 1, 0,  -sy, 0, cy};
    float Rz[9] = {cz, -sz, 0,  sz, cz, 0,  0, 0, 1};
    float RxRy[9], R[9];
    matmul3(Rx, Ry, RxRy);
    matmul3(RxRy, Rz, R);

    float Trig[16] = {
        R[0], R[1], R[2], tra[0],
        R[3], R[4], R[5], tra[1],
        R[6], R[7], R[8], tra[2],
        0.f,  0.f,  0.f,  1.f
    };

    float ref[16], flo[16];
    #pragma unroll
    for (int i = 0; i < 16; i++) { ref[i] = ref_v2r[i]; flo[i] = flo_v2r[i]; }

    float flo_inv[16], A[16], T[16];
    inv4(flo, flo_inv);
    matmul4(Trig, ref, A);
    matmul4(flo_inv, A, T);

    #pragma unroll
    for (int i = 0; i < 12; i++) g_T[i] = T[i];
}

// Pass 1: build z-pair fp16 volume; block 0 thread 0 also computes T.
__global__ void __launch_bounds__(256)
build_pairs_kernel(const float* __restrict__ X,
                   const float* __restrict__ rot,
                   const float* __restrict__ tra,
                   const float* __restrict__ ref_v2r,
                   const float* __restrict__ flo_v2r) {
    if (blockIdx.x == 0 && threadIdx.x == 0)
        compute_T(rot, tra, ref_v2r, flo_v2r);

    const int t = blockIdx.x * 256 + threadIdx.x;     // 4-voxel group id
    const int base = t << 2;
    const int kb = base & 255;                        // 0..252 step 4

    const float4 v = __ldg((const float4*)(X + base));
    const float nxt = (kb < 252) ? __ldg(X + base + 4) : v.w;

    uint4 o;
    o.x = h2_to_u32(__floats2half2_rn(v.x, v.y));
    o.y = h2_to_u32(__floats2half2_rn(v.y, v.z));
    o.z = h2_to_u32(__floats2half2_rn(v.z, v.w));
    o.w = h2_to_u32(__floats2half2_rn(v.w, nxt));
    *((uint4*)(g_pairs + base)) = o;
}

// Pass 2: 2 outputs along j per thread; pair loads, register reuse A->B.
__global__ void __launch_bounds__(256)
warp_trilinear_pairj_kernel(float* __restrict__ out) {
    const int k  = threadIdx.x;             // W (stride-1)
    const int jA = (blockIdx.x & 127) << 1; // j of output A (even)
    const int i  = blockIdx.x >> 7;         // D

    const float T00 = g_T[0], T01 = g_T[1], T02 = g_T[2],  T03 = g_T[3];
    const float T10 = g_T[4], T11 = g_T[5], T12 = g_T[6],  T13 = g_T[7];
    const float T20 = g_T[8], T21 = g_T[9], T22 = g_T[10], T23 = g_T[11];

    const float fi = (float)i, fk = (float)k;
    const float fjA = (float)jA, fjB = (float)(jA + 1);

    const float diA = fmaf(T00, fi, fmaf(T01, fjA, fmaf(T02, fk, T03)));
    const float djA = fmaf(T10, fi, fmaf(T11, fjA, fmaf(T12, fk, T13)));
    const float dkA = fmaf(T20, fi, fmaf(T21, fjA, fmaf(T22, fk, T23)));
    const float diB = diA + T01;
    const float djB = djA + T11;
    const float dkB = dkA + T21;

    const float MX = 255.f;
    const bool okA = (diA > 0.f) & (djA > 0.f) & (dkA > 0.f) &
                     (diA <= MX) & (djA <= MX) & (dkA <= MX);
    const bool okB = (diB > 0.f) & (djB > 0.f) & (dkB > 0.f) &
                     (diB <= MX) & (djB <= MX) & (dkB <= MX);

    // ---- A ----
    const float fxA = floorf(diA), fyA = floorf(djA), fzA = floorf(dkA);
    const float wcxA = diA - fxA, wfxA = 1.f - wcxA;
    const float wcyA = djA - fyA, wfyA = 1.f - wcyA;
    const float wczA = dkA - fzA, wfzA = 1.f - wczA;
    const int x0A = (int)fminf(fmaxf(fxA, 0.f), MX);
    const int y0A = (int)fminf(fmaxf(fyA, 0.f), MX);
    const int z0A = (int)fminf(fmaxf(fzA, 0.f), MX);
    const int x1A = min(x0A + 1, 255);
    const int y1A = min(y0A + 1, 255);

    const int bA00 = (x0A << 16) | (y0A << 8) | z0A;
    const int bA01 = (x0A << 16) | (y1A << 8) | z0A;
    const int bA10 = (x1A << 16) | (y0A << 8) | z0A;
    const int bA11 = (x1A << 16) | (y1A << 8) | z0A;

    const unsigned int uA00 = __ldg(g_pairs + bA00);
    const unsigned int uA01 = __ldg(g_pairs + bA01);
    const unsigned int uA10 = __ldg(g_pairs + bA10);
    const unsigned int uA11 = __ldg(g_pairs + bA11);

    // ---- B ----
    const float fxB = floorf(diB), fyB = floorf(djB), fzB = floorf(dkB);
    const float wcxB = diB - fxB, wfxB = 1.f - wcxB;
    const float wcyB = djB - fyB, wfyB = 1.f - wcyB;
    const float wczB = dkB - fzB, wfzB = 1.f - wczB;
    const int x0B = (int)fminf(fmaxf(fxB, 0.f), MX);
    const int y0B = (int)fminf(fmaxf(fyB, 0.f), MX);
    const int z0B = (int)fminf(fmaxf(fzB, 0.f), MX);
    const int x1B = min(x0B + 1, 255);
    const int y1B = min(y0B + 1, 255);

    const int bB00 = (x0B << 16) | (y0B << 8) | z0B;
    const int bB01 = (x0B << 16) | (y1B << 8) | z0B;
    const int bB10 = (x1B << 16) | (y0B << 8) | z0B;
    const int bB11 = (x1B << 16) | (y1B << 8) | z0B;

    // Reuse: if B's (x0,y0,z0) base equals A's (x0,y1,z0) base, then x,z match
    // and y0B == y1A, so A's y1-row loads are B's y0-row values (x1 follows x0).
    const bool match = (bB00 == bA01);

    unsigned int uB00, uB10;
    if (match) { uB00 = uA01; uB10 = uA11; }
    else       { uB00 = __ldg(g_pairs + bB00); uB10 = __ldg(g_pairs + bB10); }
    const unsigned int uB01 = __ldg(g_pairs + bB01);
    const unsigned int uB11 = __ldg(g_pairs + bB11);

    // ---- interpolate A ----
    const float2 pA00 = __half22float2(u32_to_h2(uA00));
    const float2 pA01 = __half22float2(u32_to_h2(uA01));
    const float2 pA10 = __half22float2(u32_to_h2(uA10));
    const float2 pA11 = __half22float2(u32_to_h2(uA11));

    const float cA00 = fmaf(pA00.x, wfzA, pA00.y * wczA);
    const float cA01 = fmaf(pA01.x, wfzA, pA01.y * wczA);
    const float cA10 = fmaf(pA10.x, wfzA, pA10.y * wczA);
    const float cA11 = fmaf(pA11.x, wfzA, pA11.y * wczA);
    const float cA0 = fmaf(cA00, wfyA, cA01 * wcyA);
    const float cA1 = fmaf(cA10, wfyA, cA11 * wcyA);
    const float vA  = fmaf(cA0, wfxA, cA1 * wcxA);

    // ---- interpolate B ----
    const float2 pB00 = __half22float2(u32_to_h2(uB00));
    const float2 pB01 = __half22float2(u32_to_h2(uB01));
    const float2 pB10 = __half22float2(u32_to_h2(uB10));
    const float2 pB11 = __half22float2(u32_to_h2(uB11));

    const float cB00 = fmaf(pB00.x, wfzB, pB00.y * wczB);
    const float cB01 = fmaf(pB01.x, wfzB, pB01.y * wczB);
    const float cB10 = fmaf(pB10.x, wfzB, pB10.y * wczB);
    const float cB11 = fmaf(pB11.x, wfzB, pB11.y * wczB);
    const float cB0 = fmaf(cB00, wfyB, cB01 * wcyB);
    const float cB1 = fmaf(cB10, wfyB, cB11 * wcyB);
    const float vB  = fmaf(cB0, wfxB, cB1 * wcxB);

    const int idxA = (i << 16) | (jA << 8) | k;
    out[idxA]       = okA ? vA : 0.f;
    out[idxA + 256] = okB ? vB : 0.f;
}

extern "C" void kernel_launch(void* const* d_in, const int* in_sizes, int n_in,
                              void* d_out, int out_size) {
    const float* image = (const float*)d_in[0];
    const float* rot   = (const float*)d_in[1];
    const float* tra   = (const float*)d_in[2];
    const float* refm  = (const float*)d_in[3];
    const float* flom  = (const float*)d_in[4];
    float* out = (float*)d_out;

    build_pairs_kernel<<<NVOX / 4 / 256, 256>>>(image, rot, tra, refm, flom);
    warp_trilinear_pairj_kernel<<<DIMD * DIMH / 2, DIMW>>>(out);
}

// round 9
// speedup vs baseline: 2.9301x; 1.1634x over previous
#include <cuda_runtime.h>
#include <cuda_bf16.h>
#include <cuda_fp16.h>
#include <math.h>

// Rigid-warp + trilinear resample of a 256^3 fp32 volume.
// Pass 1 (build): z-pair fp16 volume g_pairs[x][y][z] = half2(v[z], v[z+1]),
//   8 voxels/thread; block 0 thread 0 computes the voxel->voxel transform.
// Pass 2 (main): 2x2 outputs (i,j) per thread with chained row reuse
//   (B<-A along j, C<-A along i, D<-C along j) via packed-base matches.
// Arithmetic fp32; tap storage fp16 (rel_err ~3e-4, threshold 1e-3).

#define DIMD 256
#define DIMH 256
#define DIMW 256
#define NVOX (DIMD * DIMH * DIMW)

__device__ float g_T[12];
__device__ unsigned int g_pairs[NVOX];   // 64 MB static scratch (half2 per voxel)

static __device__ __forceinline__ unsigned int h2_to_u32(__half2 h) {
    return *reinterpret_cast<unsigned int*>(&h);
}
static __device__ __forceinline__ __half2 u32_to_h2(unsigned int u) {
    return *reinterpret_cast<__half2*>(&u);
}

__device__ __forceinline__ void matmul3(const float a[9], const float b[9], float c[9]) {
    #pragma unroll
    for (int i = 0; i < 3; i++)
        #pragma unroll
        for (int j = 0; j < 3; j++)
            c[i * 3 + j] = a[i * 3 + 0] * b[0 * 3 + j]
                         + a[i * 3 + 1] * b[1 * 3 + j]
                         + a[i * 3 + 2] * b[2 * 3 + j];
}

__device__ __forceinline__ void matmul4(const float a[16], const float b[16], float c[16]) {
    #pragma unroll
    for (int i = 0; i < 4; i++)
        #pragma unroll
        for (int j = 0; j < 4; j++)
            c[i * 4 + j] = a[i * 4 + 0] * b[0 * 4 + j]
                         + a[i * 4 + 1] * b[1 * 4 + j]
                         + a[i * 4 + 2] * b[2 * 4 + j]
                         + a[i * 4 + 3] * b[3 * 4 + j];
}

__device__ void inv4(const float m[16], float invOut[16]) {
    float inv[16];
    inv[0]  =  m[5]*m[10]*m[15] - m[5]*m[11]*m[14] - m[9]*m[6]*m[15] +
               m[9]*m[7]*m[14]  + m[13]*m[6]*m[11] - m[13]*m[7]*m[10];
    inv[4]  = -m[4]*m[10]*m[15] + m[4]*m[11]*m[14] + m[8]*m[6]*m[15] -
               m[8]*m[7]*m[14]  - m[12]*m[6]*m[11] + m[12]*m[7]*m[10];
    inv[8]  =  m[4]*m[9]*m[15]  - m[4]*m[11]*m[13] - m[8]*m[5]*m[15] +
               m[8]*m[7]*m[13]  + m[12]*m[5]*m[11] - m[12]*m[7]*m[9];
    inv[12] = -m[4]*m[9]*m[14]  + m[4]*m[10]*m[13] + m[8]*m[5]*m[14] -
               m[8]*m[6]*m[13]  - m[12]*m[5]*m[10] + m[12]*m[6]*m[9];
    inv[1]  = -m[1]*m[10]*m[15] + m[1]*m[11]*m[14] + m[9]*m[2]*m[15] -
               m[9]*m[3]*m[14]  - m[13]*m[2]*m[11] + m[13]*m[3]*m[10];
    inv[5]  =  m[0]*m[10]*m[15] - m[0]*m[11]*m[14] - m[8]*m[2]*m[15] +
               m[8]*m[3]*m[14]  + m[12]*m[2]*m[11] - m[12]*m[3]*m[10];
    inv[9]  = -m[0]*m[9]*m[15]  + m[0]*m[11]*m[13] + m[8]*m[1]*m[15] -
               m[8]*m[3]*m[13]  - m[12]*m[1]*m[11] + m[12]*m[3]*m[9];
    inv[13] =  m[0]*m[9]*m[14]  - m[0]*m[10]*m[13] - m[8]*m[1]*m[14] +
               m[8]*m[2]*m[13]  + m[12]*m[1]*m[10] - m[12]*m[2]*m[9];
    inv[2]  =  m[1]*m[6]*m[15]  - m[1]*m[7]*m[14]  - m[5]*m[2]*m[15] +
               m[5]*m[3]*m[14]  + m[13]*m[2]*m[7]  - m[13]*m[3]*m[6];
    inv[6]  = -m[0]*m[6]*m[15]  + m[0]*m[7]*m[14]  + m[4]*m[2]*m[15] -
               m[4]*m[3]*m[14]  - m[12]*m[2]*m[7]  + m[12]*m[3]*m[6];
    inv[10] =  m[0]*m[5]*m[15]  - m[0]*m[7]*m[13]  - m[4]*m[1]*m[15] +
               m[4]*m[3]*m[13]  + m[12]*m[1]*m[7]  - m[12]*m[3]*m[5];
    inv[14] = -m[0]*m[5]*m[14]  + m[0]*m[6]*m[13]  + m[4]*m[1]*m[14] -
               m[4]*m[2]*m[13]  - m[12]*m[1]*m[6]  + m[12]*m[2]*m[5];
    inv[3]  = -m[1]*m[6]*m[11]  + m[1]*m[7]*m[10]  + m[5]*m[2]*m[11] -
               m[5]*m[3]*m[10]  - m[9]*m[2]*m[7]   + m[9]*m[3]*m[6];
    inv[7]  =  m[0]*m[6]*m[11]  - m[0]*m[7]*m[10]  - m[4]*m[2]*m[11] +
               m[4]*m[3]*m[10]  + m[8]*m[2]*m[7]   - m[8]*m[3]*m[6];
    inv[11] = -m[0]*m[5]*m[11]  + m[0]*m[7]*m[9]   + m[4]*m[1]*m[11] -
               m[4]*m[3]*m[9]   - m[8]*m[1]*m[7]   + m[8]*m[3]*m[5];
    inv[15] =  m[0]*m[5]*m[10]  - m[0]*m[6]*m[9]   - m[4]*m[1]*m[10] +
               m[4]*m[2]*m[9]   + m[8]*m[1]*m[6]   - m[8]*m[2]*m[5];

    float det = m[0]*inv[0] + m[1]*inv[4] + m[2]*inv[8] + m[3]*inv[12];
    det = 1.0f / det;
    #pragma unroll
    for (int i = 0; i < 16; i++) invOut[i] = inv[i] * det;
}

__device__ void compute_T(const float* __restrict__ rot,
                          const float* __restrict__ tra,
                          const float* __restrict__ ref_v2r,
                          const float* __restrict__ flo_v2r) {
    float cx = cosf(rot[0]), cy = cosf(rot[1]), cz = cosf(rot[2]);
    float sx = sinf(rot[0]), sy = sinf(rot[1]), sz = sinf(rot[2]);

    float Rx[9] = {1, 0, 0,  0, cx, -sx,  0, sx, cx};
    float Ry[9] = {cy, 0, sy,  0, 1, 0,  -sy, 0, cy};
    float Rz[9] = {cz, -sz, 0,  sz, cz, 0,  0, 0, 1};
    float RxRy[9], R[9];
    matmul3(Rx, Ry, RxRy);
    matmul3(RxRy, Rz, R);

    float Trig[16] = {
        R[0], R[1], R[2], tra[0],
        R[3], R[4], R[5], tra[1],
        R[6], R[7], R[8], tra[2],
        0.f,  0.f,  0.f,  1.f
    };

    float ref[16], flo[16];
    #pragma unroll
    for (int i = 0; i < 16; i++) { ref[i] = ref_v2r[i]; flo[i] = flo_v2r[i]; }

    float flo_inv[16], A[16], T[16];
    inv4(flo, flo_inv);
    matmul4(Trig, ref, A);
    matmul4(flo_inv, A, T);

    #pragma unroll
    for (int i = 0; i < 12; i++) g_T[i] = T[i];
}

// Pass 1: build z-pair fp16 volume, 8 voxels per thread.
__global__ void __launch_bounds__(256)
build_pairs_kernel(const float* __restrict__ X,
                   const float* __restrict__ rot,
                   const float* __restrict__ tra,
                   const float* __restrict__ ref_v2r,
                   const float* __restrict__ flo_v2r) {
    if (blockIdx.x == 0 && threadIdx.x == 0)
        compute_T(rot, tra, ref_v2r, flo_v2r);

    const int t = blockIdx.x * 256 + threadIdx.x;     // 8-voxel group id
    const int base = t << 3;
    const int kb = base & 255;                        // 0..248 step 8

    const float4 v0 = __ldg((const float4*)(X + base));
    const float4 v1 = __ldg((const float4*)(X + base + 4));
    const float nxt = (kb < 248) ? __ldg(X + base + 8) : v1.w;

    uint4 o0, o1;
    o0.x = h2_to_u32(__floats2half2_rn(v0.x, v0.y));
    o0.y = h2_to_u32(__floats2half2_rn(v0.y, v0.z));
    o0.z = h2_to_u32(__floats2half2_rn(v0.z, v0.w));
    o0.w = h2_to_u32(__floats2half2_rn(v0.w, v1.x));
    o1.x = h2_to_u32(__floats2half2_rn(v1.x, v1.y));
    o1.y = h2_to_u32(__floats2half2_rn(v1.y, v1.z));
    o1.z = h2_to_u32(__floats2half2_rn(v1.z, v1.w));
    o1.w = h2_to_u32(__floats2half2_rn(v1.w, nxt));

    uint4* dst = (uint4*)(g_pairs + base);
    dst[0] = o0;
    dst[1] = o1;
}

// Per-output state computed from warped coords.
struct Tap {
    float wcx, wcy, wcz;
    int b00, b01, b10, b11;   // packed row-base indices (incl. z0)
    bool ok;
};

__device__ __forceinline__ Tap make_tap(float di, float dj, float dk) {
    Tap t;
    const float MX = 255.f;
    t.ok = (di > 0.f) & (dj > 0.f) & (dk > 0.f) &
           (di <= MX) & (dj <= MX) & (dk <= MX);
    const float fx = floorf(di), fy = floorf(dj), fz = floorf(dk);
    t.wcx = di - fx; t.wcy = dj - fy; t.wcz = dk - fz;
    const int x0 = (int)fminf(fmaxf(fx, 0.f), MX);
    const int y0 = (int)fminf(fmaxf(fy, 0.f), MX);
    const int z0 = (int)fminf(fmaxf(fz, 0.f), MX);
    const int x1 = min(x0 + 1, 255);
    const int y1 = min(y0 + 1, 255);
    t.b00 = (x0 << 16) | (y0 << 8) | z0;
    t.b01 = (x0 << 16) | (y1 << 8) | z0;
    t.b10 = (x1 << 16) | (y0 << 8) | z0;
    t.b11 = (x1 << 16) | (y1 << 8) | z0;
    return t;
}

__device__ __forceinline__ float interp_tap(const Tap& t,
                                            unsigned int u00, unsigned int u01,
                                            unsigned int u10, unsigned int u11) {
    const float wfz = 1.f - t.wcz, wfy = 1.f - t.wcy, wfx = 1.f - t.wcx;
    const float2 p00 = __half22float2(u32_to_h2(u00));
    const float2 p01 = __half22float2(u32_to_h2(u01));
    const float2 p10 = __half22float2(u32_to_h2(u10));
    const float2 p11 = __half22float2(u32_to_h2(u11));
    const float c00 = fmaf(p00.x, wfz, p00.y * t.wcz);
    const float c01 = fmaf(p01.x, wfz, p01.y * t.wcz);
    const float c10 = fmaf(p10.x, wfz, p10.y * t.wcz);
    const float c11 = fmaf(p11.x, wfz, p11.y * t.wcz);
    const float c0 = fmaf(c00, wfy, c01 * t.wcy);
    const float c1 = fmaf(c10, wfy, c11 * t.wcy);
    const float v  = fmaf(c0, wfx, c1 * t.wcx);
    return t.ok ? v : 0.f;
}

// Pass 2: 2x2 (i,j) outputs per thread with chained row reuse.
__global__ void __launch_bounds__(256)
warp_trilinear_quad4_kernel(float* __restrict__ out) {
    const int k  = threadIdx.x;              // W (stride-1)
    const int jA = (blockIdx.x & 127) << 1;  // even j
    const int iA = (blockIdx.x >> 7) << 1;   // even i

    const float T00 = g_T[0], T01 = g_T[1], T02 = g_T[2],  T03 = g_T[3];
    const float T10 = g_T[4], T11 = g_T[5], T12 = g_T[6],  T13 = g_T[7];
    const float T20 = g_T[8], T21 = g_T[9], T22 = g_T[10], T23 = g_T[11];

    const float fi = (float)iA, fj = (float)jA, fk = (float)k;
    const float diA = fmaf(T00, fi, fmaf(T01, fj, fmaf(T02, fk, T03)));
    const float djA = fmaf(T10, fi, fmaf(T11, fj, fmaf(T12, fk, T13)));
    const float dkA = fmaf(T20, fi, fmaf(T21, fj, fmaf(T22, fk, T23)));

    const Tap tA = make_tap(diA, djA, dkA);                      // (i, j)
    const Tap tB = make_tap(diA + T01, djA + T11, dkA + T21);    // (i, j+1)
    const Tap tC = make_tap(diA + T00, djA + T10, dkA + T20);    // (i+1, j)
    const Tap tD = make_tap(diA + T00 + T01, djA + T10 + T11,
                            dkA + T20 + T21);                    // (i+1, j+1)

    // A: 4 primary loads
    const unsigned int uA00 = __ldg(g_pairs + tA.b00);
    const unsigned int uA01 = __ldg(g_pairs + tA.b01);
    const unsigned int uA10 = __ldg(g_pairs + tA.b10);
    const unsigned int uA11 = __ldg(g_pairs + tA.b11);

    // B (j+1): reuse A's y1 rows when bases line up
    const bool mB = (tB.b00 == tA.b01);
    unsigned int uB00, uB10;
    if (mB) { uB00 = uA01; uB10 = uA11; }
    else    { uB00 = __ldg(g_pairs + tB.b00); uB10 = __ldg(g_pairs + tB.b10); }
    const unsigned int uB01 = __ldg(g_pairs + tB.b01);
    const unsigned int uB11 = __ldg(g_pairs + tB.b11);

    // C (i+1): reuse A's x1 rows
    const bool mC = (tC.b00 == tA.b10);
    unsigned int uC00, uC01;
    if (mC) { uC00 = uA10; uC01 = uA11; }
    else    { uC00 = __ldg(g_pairs + tC.b00); uC01 = __ldg(g_pairs + tC.b01); }
    const unsigned int uC10 = __ldg(g_pairs + tC.b10);
    const unsigned int uC11 = __ldg(g_pairs + tC.b11);

    // D (i+1, j+1): reuse C's y1 rows
    const bool mD = (tD.b00 == tC.b01);
    unsigned int uD00, uD10;
    if (mD) { uD00 = uC01; uD10 = uC11; }
    else    { uD00 = __ldg(g_pairs + tD.b00); uD10 = __ldg(g_pairs + tD.b10); }
    const unsigned int uD01 = __ldg(g_pairs + tD.b01);
    const unsigned int uD11 = __ldg(g_pairs + tD.b11);

    const float vA = interp_tap(tA, uA00, uA01, uA10, uA11);
    const float vB = interp_tap(tB, uB00, uB01, uB10, uB11);
    const float vC = interp_tap(tC, uC00, uC01, uC10, uC11);
    const float vD = interp_tap(tD, uD00, uD01, uD10, uD11);

    const int idxA = (iA << 16) | (jA << 8) | k;
    out[idxA]               = vA;
    out[idxA + 256]         = vB;
    out[idxA + 65536]       = vC;
    out[idxA + 65536 + 256] = vD;
}

extern "C" void kernel_launch(void* const* d_in, const int* in_sizes, int n_in,
                              void* d_out, int out_size) {
    const float* image = (const float*)d_in[0];
    const float* rot   = (const float*)d_in[1];
    const float* tra   = (const float*)d_in[2];
    const float* refm  = (const float*)d_in[3];
    const float* flom  = (const float*)d_in[4];
    float* out = (float*)d_out;

    build_pairs_kernel<<<NVOX / 8 / 256, 256>>>(image, rot, tra, refm, flom);
    warp_trilinear_quad4_kernel<<<(DIMD / 2) * (DIMH / 2), DIMW>>>(out);
}

// round 10
// speedup vs baseline: 2.9531x; 1.0078x over previous
#include <cuda_runtime.h>
#include <cuda_bf16.h>
#include <cuda_fp16.h>
#include <math.h>

// Rigid-warp + trilinear resample of a 256^3 fp32 volume.
// Pass 1 (build): z-pair fp16 volume g_pairs[x][y][z] = half2(v[z], v[z+1]),
//   8 voxels/thread; block 0 thread 0 computes the voxel->voxel transform.
// Then a 48-byte D2D memcpy promotes T into __constant__ memory.
// Pass 2 (main): 2x2 outputs (i,j) per thread with chained row reuse,
//   lerp-form interpolation, incremental packed-base indices.
// Arithmetic fp32; tap storage fp16 (rel_err ~3e-4, threshold 1e-3).

#define DIMD 256
#define DIMH 256
#define DIMW 256
#define NVOX (DIMD * DIMH * DIMW)

__device__ float g_T[12];
__constant__ float c_T[12];
__device__ unsigned int g_pairs[NVOX];   // 64 MB static scratch (half2 per voxel)

static __device__ __forceinline__ unsigned int h2_to_u32(__half2 h) {
    return *reinterpret_cast<unsigned int*>(&h);
}
static __device__ __forceinline__ __half2 u32_to_h2(unsigned int u) {
    return *reinterpret_cast<__half2*>(&u);
}

__device__ __forceinline__ void matmul3(const float a[9], const float b[9], float c[9]) {
    #pragma unroll
    for (int i = 0; i < 3; i++)
        #pragma unroll
        for (int j = 0; j < 3; j++)
            c[i * 3 + j] = a[i * 3 + 0] * b[0 * 3 + j]
                         + a[i * 3 + 1] * b[1 * 3 + j]
                         + a[i * 3 + 2] * b[2 * 3 + j];
}

__device__ __forceinline__ void matmul4(const float a[16], const float b[16], float c[16]) {
    #pragma unroll
    for (int i = 0; i < 4; i++)
        #pragma unroll
        for (int j = 0; j < 4; j++)
            c[i * 4 + j] = a[i * 4 + 0] * b[0 * 4 + j]
                         + a[i * 4 + 1] * b[1 * 4 + j]
                         + a[i * 4 + 2] * b[2 * 4 + j]
                         + a[i * 4 + 3] * b[3 * 4 + j];
}

__device__ void inv4(const float m[16], float invOut[16]) {
    float inv[16];
    inv[0]  =  m[5]*m[10]*m[15] - m[5]*m[11]*m[14] - m[9]*m[6]*m[15] +
               m[9]*m[7]*m[14]  + m[13]*m[6]*m[11] - m[13]*m[7]*m[10];
    inv[4]  = -m[4]*m[10]*m[15] + m[4]*m[11]*m[14] + m[8]*m[6]*m[15] -
               m[8]*m[7]*m[14]  - m[12]*m[6]*m[11] + m[12]*m[7]*m[10];
    inv[8]  =  m[4]*m[9]*m[15]  - m[4]*m[11]*m[13] - m[8]*m[5]*m[15] +
               m[8]*m[7]*m[13]  + m[12]*m[5]*m[11] - m[12]*m[7]*m[9];
    inv[12] = -m[4]*m[9]*m[14]  + m[4]*m[10]*m[13] + m[8]*m[5]*m[14] -
               m[8]*m[6]*m[13]  - m[12]*m[5]*m[10] + m[12]*m[6]*m[9];
    inv[1]  = -m[1]*m[10]*m[15] + m[1]*m[11]*m[14] + m[9]*m[2]*m[15] -
               m[9]*m[3]*m[14]  - m[13]*m[2]*m[11] + m[13]*m[3]*m[10];
    inv[5]  =  m[0]*m[10]*m[15] - m[0]*m[11]*m[14] - m[8]*m[2]*m[15] +
               m[8]*m[3]*m[14]  + m[12]*m[2]*m[11] - m[12]*m[3]*m[10];
    inv[9]  = -m[0]*m[9]*m[15]  + m[0]*m[11]*m[13] + m[8]*m[1]*m[15] -
               m[8]*m[3]*m[13]  - m[12]*m[1]*m[11] + m[12]*m[3]*m[9];
    inv[13] =  m[0]*m[9]*m[14]  - m[0]*m[10]*m[13] - m[8]*m[1]*m[14] +
               m[8]*m[2]*m[13]  + m[12]*m[1]*m[10] - m[12]*m[2]*m[9];
    inv[2]  =  m[1]*m[6]*m[15]  - m[1]*m[7]*m[14]  - m[5]*m[2]*m[15] +
               m[5]*m[3]*m[14]  + m[13]*m[2]*m[7]  - m[13]*m[3]*m[6];
    inv[6]  = -m[0]*m[6]*m[15]  + m[0]*m[7]*m[14]  + m[4]*m[2]*m[15] -
               m[4]*m[3]*m[14]  - m[12]*m[2]*m[7]  + m[12]*m[3]*m[6];
    inv[10] =  m[0]*m[5]*m[15]  - m[0]*m[7]*m[13]  - m[4]*m[1]*m[15] +
               m[4]*m[3]*m[13]  + m[12]*m[1]*m[7]  - m[12]*m[3]*m[5];
    inv[14] = -m[0]*m[5]*m[14]  + m[0]*m[6]*m[13]  + m[4]*m[1]*m[14] -
               m[4]*m[2]*m[13]  - m[12]*m[1]*m[6]  + m[12]*m[2]*m[5];
    inv[3]  = -m[1]*m[6]*m[11]  + m[1]*m[7]*m[10]  + m[5]*m[2]*m[11] -
               m[5]*m[3]*m[10]  - m[9]*m[2]*m[7]   + m[9]*m[3]*m[6];
    inv[7]  =  m[0]*m[6]*m[11]  - m[0]*m[7]*m[10]  - m[4]*m[2]*m[11] +
               m[4]*m[3]*m[10]  + m[8]*m[2]*m[7]   - m[8]*m[3]*m[6];
    inv[11] = -m[0]*m[5]*m[11]  + m[0]*m[7]*m[9]   + m[4]*m[1]*m[11] -
               m[4]*m[3]*m[9]   - m[8]*m[1]*m[7]   + m[8]*m[3]*m[5];
    inv[15] =  m[0]*m[5]*m[10]  - m[0]*m[6]*m[9]   - m[4]*m[1]*m[10] +
               m[4]*m[2]*m[9]   + m[8]*m[1]*m[6]   - m[8]*m[2]*m[5];

    float det = m[0]*inv[0] + m[1]*inv[4] + m[2]*inv[8] + m[3]*inv[12];
    det = 1.0f / det;
    #pragma unroll
    for (int i = 0; i < 16; i++) invOut[i] = inv[i] * det;
}

__device__ void compute_T(const float* __restrict__ rot,
                          const float* __restrict__ tra,
                          const float* __restrict__ ref_v2r,
                          const float* __restrict__ flo_v2r) {
    float cx = cosf(rot[0]), cy = cosf(rot[1]), cz = cosf(rot[2]);
    float sx = sinf(rot[0]), sy = sinf(rot[1]), sz = sinf(rot[2]);

    float Rx[9] = {1, 0, 0,  0, cx, -sx,  0, sx, cx};
    float Ry[9] = {cy, 0, sy,  0, 1, 0,  -sy, 0, cy};
    float Rz[9] = {cz, -sz, 0,  sz, cz, 0,  0, 0, 1};
    float RxRy[9], R[9];
    matmul3(Rx, Ry, RxRy);
    matmul3(RxRy, Rz, R);

    float Trig[16] = {
        R[0], R[1], R[2], tra[0],
        R[3], R[4], R[5], tra[1],
        R[6], R[7], R[8], tra[2],
        0.f,  0.f,  0.f,  1.f
    };

    float ref[16], flo[16];
    #pragma unroll
    for (int i = 0; i < 16; i++) { ref[i] = ref_v2r[i]; flo[i] = flo_v2r[i]; }

    float flo_inv[16], A[16], T[16];
    inv4(flo, flo_inv);
    matmul4(Trig, ref, A);
    matmul4(flo_inv, A, T);

    #pragma unroll
    for (int i = 0; i < 12; i++) g_T[i] = T[i];
}

// Pass 1: build z-pair fp16 volume, 8 voxels per thread.
__global__ void __launch_bounds__(256)
build_pairs_kernel(const float* __restrict__ X,
                   const float* __restrict__ rot,
                   const float* __restrict__ tra,
                   const float* __restrict__ ref_v2r,
                   const float* __restrict__ flo_v2r) {
    if (blockIdx.x == 0 && threadIdx.x == 0)
        compute_T(rot, tra, ref_v2r, flo_v2r);

    const int t = blockIdx.x * 256 + threadIdx.x;     // 8-voxel group id
    const int base = t << 3;
    const int kb = base & 255;                        // 0..248 step 8

    const float4 v0 = __ldg((const float4*)(X + base));
    const float4 v1 = __ldg((const float4*)(X + base + 4));
    const float nxt = (kb < 248) ? __ldg(X + base + 8) : v1.w;

    uint4 o0, o1;
    o0.x = h2_to_u32(__floats2half2_rn(v0.x, v0.y));
    o0.y = h2_to_u32(__floats2half2_rn(v0.y, v0.z));
    o0.z = h2_to_u32(__floats2half2_rn(v0.z, v0.w));
    o0.w = h2_to_u32(__floats2half2_rn(v0.w, v1.x));
    o1.x = h2_to_u32(__floats2half2_rn(v1.x, v1.y));
    o1.y = h2_to_u32(__floats2half2_rn(v1.y, v1.z));
    o1.z = h2_to_u32(__floats2half2_rn(v1.z, v1.w));
    o1.w = h2_to_u32(__floats2half2_rn(v1.w, nxt));

    uint4* dst = (uint4*)(g_pairs + base);
    dst[0] = o0;
    dst[1] = o1;
}

// Per-output state.
struct Tap {
    float wcx, wcy, wcz;
    int b00, dx, dy;          // packed base + row deltas (0 or 65536 / 256)
    bool ok;
};

__device__ __forceinline__ Tap make_tap(float di, float dj, float dk) {
    Tap t;
    const float MX = 255.f;
    t.ok = (di > 0.f) & (dj > 0.f) & (dk > 0.f) &
           (di <= MX) & (dj <= MX) & (dk <= MX);
    const float fx = floorf(di), fy = floorf(dj), fz = floorf(dk);
    t.wcx = di - fx; t.wcy = dj - fy; t.wcz = dk - fz;
    const int x0 = (int)fminf(fmaxf(fx, 0.f), MX);
    const int y0 = (int)fminf(fmaxf(fy, 0.f), MX);
    const int z0 = (int)fminf(fmaxf(fz, 0.f), MX);
    t.b00 = (x0 << 16) | (y0 << 8) | z0;
    t.dx = (x0 < 255) ? 65536 : 0;
    t.dy = (y0 < 255) ? 256 : 0;
    return t;
}

__device__ __forceinline__ float lerpf(float a, float b, float w) {
    return fmaf(w, b - a, a);
}

__device__ __forceinline__ float interp_tap(const Tap& t,
                                            unsigned int u00, unsigned int u01,
                                            unsigned int u10, unsigned int u11) {
    const float2 p00 = __half22float2(u32_to_h2(u00));
    const float2 p01 = __half22float2(u32_to_h2(u01));
    const float2 p10 = __half22float2(u32_to_h2(u10));
    const float2 p11 = __half22float2(u32_to_h2(u11));
    const float c00 = lerpf(p00.x, p00.y, t.wcz);
    const float c01 = lerpf(p01.x, p01.y, t.wcz);
    const float c10 = lerpf(p10.x, p10.y, t.wcz);
    const float c11 = lerpf(p11.x, p11.y, t.wcz);
    const float c0 = lerpf(c00, c01, t.wcy);
    const float c1 = lerpf(c10, c11, t.wcy);
    const float v  = lerpf(c0, c1, t.wcx);
    return t.ok ? v : 0.f;
}

// Pass 2: 2x2 (i,j) outputs per thread with chained row reuse.
__global__ void __launch_bounds__(256)
warp_trilinear_quad4_kernel(float* __restrict__ out) {
    const int k  = threadIdx.x;              // W (stride-1)
    const int jA = (blockIdx.x & 127) << 1;  // even j
    const int iA = (blockIdx.x >> 7) << 1;   // even i

    const float T00 = c_T[0], T01 = c_T[1], T02 = c_T[2],  T03 = c_T[3];
    const float T10 = c_T[4], T11 = c_T[5], T12 = c_T[6],  T13 = c_T[7];
    const float T20 = c_T[8], T21 = c_T[9], T22 = c_T[10], T23 = c_T[11];

    const float fi = (float)iA, fj = (float)jA, fk = (float)k;
    const float diA = fmaf(T00, fi, fmaf(T01, fj, fmaf(T02, fk, T03)));
    const float djA = fmaf(T10, fi, fmaf(T11, fj, fmaf(T12, fk, T13)));
    const float dkA = fmaf(T20, fi, fmaf(T21, fj, fmaf(T22, fk, T23)));

    const Tap tA = make_tap(diA, djA, dkA);                      // (i, j)
    const Tap tB = make_tap(diA + T01, djA + T11, dkA + T21);    // (i, j+1)
    const Tap tC = make_tap(diA + T00, djA + T10, dkA + T20);    // (i+1, j)
    const Tap tD = make_tap(diA + T00 + T01, djA + T10 + T11,
                            dkA + T20 + T21);                    // (i+1, j+1)

    const int bA01 = tA.b00 + tA.dy;
    const int bA10 = tA.b00 + tA.dx;
    const int bA11 = bA10 + tA.dy;

    const unsigned int uA00 = __ldg(g_pairs + tA.b00);
    const unsigned int uA01 = __ldg(g_pairs + bA01);
    const unsigned int uA10 = __ldg(g_pairs + bA10);
    const unsigned int uA11 = __ldg(g_pairs + bA11);

    // B (j+1): reuse A's y1 rows when bases line up
    const bool mB = (tB.b00 == bA01);
    unsigned int uB00, uB10;
    if (mB) { uB00 = uA01; uB10 = uA11; }
    else    { uB00 = __ldg(g_pairs + tB.b00);
              uB10 = __ldg(g_pairs + tB.b00 + tB.dx); }
    const unsigned int uB01 = __ldg(g_pairs + tB.b00 + tB.dy);
    const unsigned int uB11 = __ldg(g_pairs + tB.b00 + tB.dx + tB.dy);

    // C (i+1): reuse A's x1 rows
    const bool mC = (tC.b00 == bA10);
    unsigned int uC00, uC01;
    if (mC) { uC00 = uA10; uC01 = uA11; }
    else    { uC00 = __ldg(g_pairs + tC.b00);
              uC01 = __ldg(g_pairs + tC.b00 + tC.dy); }
    const int bC10 = tC.b00 + tC.dx;
    const unsigned int uC10 = __ldg(g_pairs + bC10);
    const unsigned int uC11 = __ldg(g_pairs + bC10 + tC.dy);

    // D (i+1, j+1): reuse C's y1 rows
    const bool mD = (tD.b00 == tC.b00 + tC.dy);
    unsigned int uD00, uD10;
    if (mD) { uD00 = uC01; uD10 = uC11; }
    else    { uD00 = __ldg(g_pairs + tD.b00);
              uD10 = __ldg(g_pairs + tD.b00 + tD.dx); }
    const unsigned int uD01 = __ldg(g_pairs + tD.b00 + tD.dy);
    const unsigned int uD11 = __ldg(g_pairs + tD.b00 + tD.dx + tD.dy);

    const float vA = interp_tap(tA, uA00, uA01, uA10, uA11);
    const float vB = interp_tap(tB, uB00, uB01, uB10, uB11);
    const float vC = interp_tap(tC, uC00, uC01, uC10, uC11);
    const float vD = interp_tap(tD, uD00, uD01, uD10, uD11);

    const int idxA = (iA << 16) | (jA << 8) | k;
    out[idxA]               = vA;
    out[idxA + 256]         = vB;
    out[idxA + 65536]       = vC;
    out[idxA + 65536 + 256] = vD;
}

extern "C" void kernel_launch(void* const* d_in, const int* in_sizes, int n_in,
                              void* d_out, int out_size) {
    const float* image = (const float*)d_in[0];
    const float* rot   = (const float*)d_in[1];
    const float* tra   = (const float*)d_in[2];
    const float* refm  = (const float*)d_in[3];
    const float* flom  = (const float*)d_in[4];
    float* out = (float*)d_out;

    build_pairs_kernel<<<NVOX / 8 / 256, 256>>>(image, rot, tra, refm, flom);

    // Promote T from __device__ to __constant__ (48-byte D2D, capturable).
    void* src = nullptr;
    cudaGetSymbolAddress(&src, g_T);
    cudaMemcpyToSymbolAsync(c_T, src, 12 * sizeof(float), 0,
                            cudaMemcpyDeviceToDevice);

    warp_trilinear_quad4_kernel<<<(DIMD / 2) * (DIMH / 2), DIMW>>>(out);
}